// round 6
// baseline (speedup 1.0000x reference)
#include <cuda_runtime.h>

#define SDIM 56
#define NCELL 3136
#define NITEM 6272
#define NCLS 20
#define IMG_STRIDE 94080
#define CONF_OFF 62720
#define COORD_OFF 68992
#define MAXOUT 30
#define NCAND 256
#define KEYBUF 2048
#define BATCH 256
#define NT 512

__device__ float g_scores[BATCH * NITEM];
__device__ unsigned char g_cls[BATCH * NITEM];

// ---------------------------------------------------------------------------
// Kernel 1: decode scores + argmax class for every (cell, box). One thread/cell.
// ---------------------------------------------------------------------------
__global__ __launch_bounds__(256) void decode_kernel(const float* __restrict__ in)
{
    int gcell = blockIdx.x * 256 + threadIdx.x;
    if (gcell >= BATCH * NCELL) return;
    int img  = gcell / NCELL;
    int cell = gcell - img * NCELL;

    const float* base = in + (long)img * IMG_STRIDE;
    const float4* cp = (const float4*)(base + cell * NCLS);
    float p[NCLS];
    #pragma unroll
    for (int k = 0; k < 5; ++k) {
        float4 v = cp[k];
        p[4*k+0] = v.x; p[4*k+1] = v.y; p[4*k+2] = v.z; p[4*k+3] = v.w;
    }
    const float2 cf = *(const float2*)(base + CONF_OFF + cell * 2);
    float b0 = -1.0f, b1 = -1.0f;
    int a0 = 0, a1 = 0;
    #pragma unroll
    for (int c = 0; c < NCLS; ++c) {
        float v0 = cf.x * p[c];
        float v1 = cf.y * p[c];
        if (v0 > b0) { b0 = v0; a0 = c; }
        if (v1 > b1) { b1 = v1; a1 = c; }
    }
    float s0 = (b0 >= 0.1f) ? b0 : 0.0f;
    float s1 = (b1 >= 0.1f) ? b1 : 0.0f;
    long o = (long)img * NITEM + cell * 2;
    *(float2*)(g_scores + o) = make_float2(s0, s1);
    g_cls[o + 0] = (unsigned char)a0;
    g_cls[o + 1] = (unsigned char)a1;
}

// warp-wide 32x32 bit-matrix transpose: lane l holds row l; returns column 'lane'
__device__ __forceinline__ unsigned warp_bit_transpose(unsigned x, int lane)
{
    unsigned y, m;
    m = 0x0000FFFFu; y = __shfl_xor_sync(0xFFFFFFFFu, x, 16);
    x = ((lane & 16) == 0) ? ((x & m) | ((y & m) << 16)) : ((x & ~m) | ((y >> 16) & m));
    m = 0x00FF00FFu; y = __shfl_xor_sync(0xFFFFFFFFu, x, 8);
    x = ((lane & 8) == 0) ? ((x & m) | ((y & m) << 8)) : ((x & ~m) | ((y >> 8) & m));
    m = 0x0F0F0F0Fu; y = __shfl_xor_sync(0xFFFFFFFFu, x, 4);
    x = ((lane & 4) == 0) ? ((x & m) | ((y & m) << 4)) : ((x & ~m) | ((y >> 4) & m));
    m = 0x33333333u; y = __shfl_xor_sync(0xFFFFFFFFu, x, 2);
    x = ((lane & 2) == 0) ? ((x & m) | ((y & m) << 2)) : ((x & ~m) | ((y >> 2) & m));
    m = 0x55555555u; y = __shfl_xor_sync(0xFFFFFFFFu, x, 1);
    x = ((lane & 1) == 0) ? ((x & m) | ((y & m) << 1)) : ((x & ~m) | ((y >> 1) & m));
    return x;
}

// ---------------------------------------------------------------------------
// Kernel 2: per-image top-256 selection + greedy NMS. One block (512t) per image.
// ---------------------------------------------------------------------------
__global__ __launch_bounds__(NT, 2) void nms_kernel(const float* __restrict__ in,
                                                    float* __restrict__ out)
{
    __shared__ float sc[NITEM];                               // scores; SoA overlay later
    __shared__ __align__(16) unsigned long long keys[KEYBUF];
    __shared__ int whist[16][32];
    __shared__ int picks[MAXOUT];
    __shared__ unsigned int wvalid[2][8];
    __shared__ int s_binsel;
    __shared__ int s_cnt;

    const int img = blockIdx.x;
    const int t = threadIdx.x;
    const int lane = t & 31;
    const int warp = t >> 5;
    const float* coord = in + (long)img * IMG_STRIDE + COORD_OFF;
    const float* gs = g_scores + (long)img * NITEM;
    const unsigned char* gc = g_cls + (long)img * NITEM;

    // ---- Phase A: load scores into smem ----
    for (int i = t; i < NITEM / 4; i += NT)
        ((float4*)sc)[i] = ((const float4*)gs)[i];
    if (t == 0) s_cnt = 0;
    __syncthreads();

    // ---- Phase B: atomic-free 32-bin coarse histogram (warp bit transpose) ----
    unsigned acc = 0;                      // lane owns coarse bin 'lane'
    for (int i = t; i < NITEM; i += NT) {  // full warps only at every batch (6272 = 196*32)
        float s = sc[i];
        int b = (int)(s * 1024.0f);
        b = b < 0 ? 0 : (b > 1023 ? 1023 : b);
        unsigned x = warp_bit_transpose(1u << (b >> 5), lane);
        acc += __popc(x);
    }
    whist[warp][lane] = (int)acc;
    __syncthreads();
    if (warp == 0) {
        int v = 0;
        #pragma unroll
        for (int w2 = 0; w2 < 16; ++w2) v += whist[w2][lane];
        int ss = v;                         // inclusive suffix over bins (bin = lane)
        #pragma unroll
        for (int off = 1; off < 32; off <<= 1) {
            int o = __shfl_down_sync(0xFFFFFFFFu, ss, off);
            if (lane + off < 32) ss += o;
        }
        unsigned m2 = __ballot_sync(0xFFFFFFFFu, ss >= NCAND);  // nonzero: total >= 256
        int bstar0 = 31 - __clz(m2);        // largest coarse bin with suffix >= 256
        if (lane == 0) s_binsel = bstar0 << 5;
    }
    __syncthreads();
    const int bstar = s_binsel;             // threshold in 1024-bin units

    // ---- Phase C: gather survivor keys (superset of top-256) ----
    // key = score_bits(31b) << 13 | (8191 - idx): desc key order == lax.top_k order
    for (int i = t; i < NITEM; i += NT) {
        float s = sc[i];
        int b = (int)(s * 1024.0f);
        b = b < 0 ? 0 : (b > 1023 ? 1023 : b);
        if (b >= bstar) {
            int pos = atomicAdd(&s_cnt, 1);
            if (pos < KEYBUF) {
                unsigned long long key =
                    ((unsigned long long)__float_as_uint(s) << 13) |
                    (unsigned long long)(8191 - i);
                keys[pos] = key;
            }
        }
    }
    __syncthreads();
    int n = s_cnt; if (n > KEYBUF) n = KEYBUF;
    int np = NT; while (np < n) np <<= 1;
    for (int i = n + t; i < np; i += NT) keys[i] = 0ull;
    __syncthreads();

    // ---- Phase D: bitonic sort descending ----
    unsigned long long a = keys[t];
    if (np == NT) {
        #pragma unroll
        for (int k = 2; k <= NT; k <<= 1) {
            #pragma unroll
            for (int j = k >> 1; j > 0; j >>= 1) {
                bool up = ((t & k) == 0);
                unsigned long long b2;
                if (j >= 32) {
                    __syncthreads();
                    keys[t] = a;
                    __syncthreads();
                    b2 = keys[t ^ j];
                } else {
                    b2 = __shfl_xor_sync(0xFFFFFFFFu, a, j);
                }
                bool keep_max = (up == ((t & j) == 0));
                bool amax = (a > b2);
                a = (keep_max == amax) ? a : b2;
            }
        }
    } else {
        for (int k = 2; k <= np; k <<= 1) {
            for (int j = k >> 1; j > 0; j >>= 1) {
                for (int i = t; i < np; i += NT) {
                    int ixj = i ^ j;
                    if (ixj > i) {
                        unsigned long long x = keys[i];
                        unsigned long long y = keys[ixj];
                        bool up = ((i & k) == 0);
                        bool doswap = up ? (x < y) : (x > y);
                        if (doswap) { keys[i] = y; keys[ixj] = x; }
                    }
                }
                __syncthreads();
            }
        }
        a = keys[t];
    }
    __syncthreads();

    // ---- Phase E: build candidate SoA (overlay on sc); init validity ----
    float* cy0  = sc;
    float* cx0  = sc + 256;
    float* cy1  = sc + 512;
    float* cx1  = sc + 768;
    float* cscv = sc + 1024;
    float* cclv = sc + 1280;
    if (t < NCAND) {
        int idx = 8191 - (int)(a & 0x1FFFull);
        float s = __uint_as_float((unsigned)(a >> 13));
        float y0 = 0.f, x0 = 0.f, y1 = 0.f, x1 = 0.f, cl = 0.f;
        if (idx < NITEM) {
            int cell = idx >> 1;
            int bb = idx & 1;
            int ci = cell / SDIM;
            int cj = cell - ci * SDIM;
            float4 cd = *(const float4*)(coord + ((long)cell * 2 + bb) * 4);
            float x = __fdiv_rn(cd.x + (float)cj, 56.0f);
            float y = __fdiv_rn(cd.y + (float)ci, 56.0f);
            float wh = (cd.z * cd.z) * 0.5f;
            float hh = (cd.w * cd.w) * 0.5f;
            y0 = y - hh; x0 = x - wh; y1 = y + hh; x1 = x + wh;
            cl = (float)gc[idx];
        } else {
            s = 0.0f;
        }
        cy0[t] = y0; cx0[t] = x0; cy1[t] = y1; cx1[t] = x1; cscv[t] = s; cclv[t] = cl;
    }
    if (t < 8) wvalid[0][t] = 0xFFFFFFFFu;
    __syncthreads();

    // ---- Phase F: greedy NMS on warps 0..7; shfl-based pick; one sync/round ----
    float my_y0 = 0.f, my_x0 = 0.f, my_y1 = 0.f, my_x1 = 0.f, my_area = 0.f;
    if (warp < 8) {
        my_y0 = cy0[t]; my_x0 = cx0[t]; my_y1 = cy1[t]; my_x1 = cx1[t];
        my_area = __fmul_rn(fmaxf(my_y1 - my_y0, 0.0f), fmaxf(my_x1 - my_x0, 0.0f));
    }
    for (int r = 0; r < MAXOUT; ++r) {
        const int cur = r & 1;
        if (warp < 8) {
            unsigned w = wvalid[cur][lane & 7];          // lanes 0..7 carry the 8 words
            unsigned nz = __ballot_sync(0xFFFFFFFFu, (lane < 8) && (w != 0u));
            int p = -1;
            if (nz) {
                int lf = __ffs(nz) - 1;
                unsigned wlf = __shfl_sync(0xFFFFFFFFu, w, lf);
                p = lf * 32 + __ffs(wlf) - 1;            // first valid (sorted => argmax)
            }
            if (t == 0) picks[r] = p;
            unsigned wown = __shfl_sync(0xFFFFFFFFu, w, warp);
            bool nv = (wown >> lane) & 1u;
            if (p >= 0) {
                float py0 = cy0[p], px0 = cx0[p], py1 = cy1[p], px1 = cx1[p];
                float parea = __fmul_rn(fmaxf(py1 - py0, 0.0f), fmaxf(px1 - px0, 0.0f));
                float iy = fmaxf(0.0f, fminf(py1, my_y1) - fmaxf(py0, my_y0));
                float ix = fmaxf(0.0f, fminf(px1, my_x1) - fmaxf(px0, my_x0));
                float inter = __fmul_rn(iy, ix);
                float uni = parea + my_area - inter;
                float iou = (uni > 0.0f) ? __fdiv_rn(inter, uni) : 0.0f;
                if (iou > 0.4f) nv = false;
                if (t == p) nv = false;
            }
            unsigned bal = __ballot_sync(0xFFFFFFFFu, nv);
            if (lane == 0) wvalid[cur ^ 1][warp] = bal;
        }
        __syncthreads();
    }

    // ---- parallel output write: 30 rows x 6 comps ----
    if (t < MAXOUT * 6) {
        int r = t / 6, c = t - r * 6;
        int p = picks[r];
        float v = 0.0f;
        if (p >= 0) v = sc[c * 256 + p];   // SoA contiguous: [y0,x0,y1,x1,score,class]
        out[(long)img * (MAXOUT * 6) + t] = v;
    }
}

extern "C" void kernel_launch(void* const* d_in, const int* in_sizes, int n_in,
                              void* d_out, int out_size)
{
    const float* in = (const float*)d_in[0];
    float* out = (float*)d_out;
    decode_kernel<<<(BATCH * NCELL + 255) / 256, 256>>>(in);
    nms_kernel<<<BATCH, NT>>>(in, out);
}